// round 17
// baseline (speedup 1.0000x reference)
#include <cuda_runtime.h>
#include <cstdint>

#define PP     8
#define FF     64
#define SB     200
#define HB     100                      // rows per CTA (half batch)
#define TPB    224                      // 7 warps = 7 m16 tiles
#define VPITCH 272u                     // 17 x 16B: odd pitch -> conflict-free ldmatrix
#define U_OFF  (HB * (int)VPITCH)       // 27200
#define SMEMB  (U_OFF + PP * (int)VPITCH)   // 29376 -> 7 CTAs/SM
#define TXB    ((HB + PP) * 256)        // 27648 expected tx bytes

typedef unsigned long long ull;

static __device__ __forceinline__ void bulk_cp(uint32_t dst, const void* src,
                                               uint32_t bytes, uint32_t mbar) {
    asm volatile("cp.async.bulk.shared::cta.global.mbarrier::complete_tx::bytes [%0], [%1], %2, [%3];"
                 :: "r"(dst), "l"(src), "r"(bytes), "r"(mbar) : "memory");
}
static __device__ __forceinline__ void mbar_wait(uint32_t addr) {
    asm volatile(
        "{\n\t.reg .pred P;\n\t"
        "LAB_%=:\n\t"
        "mbarrier.try_wait.parity.acquire.cta.shared::cta.b64 P, [%0], 0, 0x989680;\n\t"
        "@!P bra LAB_%=;\n\t}"
        :: "r"(addr) : "memory");
}
// B operand: RNA-rounded tf32 (precision margin; once per warp)
static __device__ __forceinline__ uint32_t lds_tf32(uint32_t addr) {
    float v; asm volatile("ld.shared.f32 %0, [%1];" : "=f"(v) : "r"(addr));
    uint32_t o; asm("cvt.rna.tf32.f32 %0, %1;" : "=r"(o) : "f"(v));
    return o;
}
static __device__ __forceinline__ void ldsm4(uint32_t& a0, uint32_t& a1,
                                             uint32_t& a2, uint32_t& a3, uint32_t addr) {
    asm volatile("ldmatrix.sync.aligned.m8n8.x4.shared.b16 {%0,%1,%2,%3}, [%4];"
                 : "=r"(a0), "=r"(a1), "=r"(a2), "=r"(a3) : "r"(addr));
}
static __device__ __forceinline__ void mma_tf32(float& d0, float& d1, float& d2, float& d3,
                                                uint32_t a0, uint32_t a1, uint32_t a2, uint32_t a3,
                                                uint32_t b0, uint32_t b1) {
    asm volatile("mma.sync.aligned.m16n8k8.row.col.f32.tf32.tf32.f32 "
                 "{%0,%1,%2,%3}, {%4,%5,%6,%7}, {%8,%9}, {%0,%1,%2,%3};"
                 : "+f"(d0), "+f"(d1), "+f"(d2), "+f"(d3)
                 : "r"(a0), "r"(a1), "r"(a2), "r"(a3), "r"(b0), "r"(b1));
}

// Per-row epilogue; all lanes run shuffles, 'wr' guards the stores.
static __device__ __forceinline__ void emit_row(long long b, int row, int q, bool wr,
                                                float r0, float r1,
                                                float* __restrict__ pred,
                                                float* __restrict__ scores) {
    const float e0 = __expf(r0), e1 = __expf(r1);
    float s = e0 + e1;
    float p = fmaf(e1, r1, e0 * r0);
    s += __shfl_xor_sync(0xFFFFFFFFu, s, 1);
    p += __shfl_xor_sync(0xFFFFFFFFu, p, 1);
    s += __shfl_xor_sync(0xFFFFFFFFu, s, 2);
    p += __shfl_xor_sync(0xFFFFFFFFu, p, 2);
    const float inv = 1.f / s;
    if (wr) {
        const long long g = b * SB + row;
        *(float2*)(scores + g * (long long)PP + 2 * q) = make_float2(e0 * inv, e1 * inv);
        if (q == 0) pred[g] = p * inv;
    }
}

__global__ __launch_bounds__(TPB, 7) void cf_kernel(
    const int*   __restrict__ user,     // [B]
    const int*   __restrict__ items,    // [B,SB]
    const float* __restrict__ ufac,     // [N_USERS, PP, FF]
    const float* __restrict__ ifac,     // [N_ITEMS, FF]
    float*       __restrict__ pred,     // [B,SB]
    float*       __restrict__ scores)   // [B,SB,PP]
{
    extern __shared__ __align__(16) char smem[];
    __shared__ __align__(8) ull mbar;

    const int tid  = threadIdx.x;
    const int wid  = tid >> 5;
    const int lane = tid & 31;
    const int q    = lane & 3;
    const int gp   = lane >> 2;
    const long long b = blockIdx.x >> 1;
    const int ro = (blockIdx.x & 1) * HB;      // row offset within batch

    const uint32_t sv = (uint32_t)__cvta_generic_to_shared(smem);
    const uint32_t su = sv + (uint32_t)U_OFF;
    const uint32_t mb = (uint32_t)__cvta_generic_to_shared(&mbar);

    if (tid == 0)
        asm volatile("mbarrier.init.shared.b64 [%0], 1;" :: "r"(mb) : "memory");
    __syncthreads();

    // ---- Gather via bulk DMA: one 256B copy per V row + 8 for U rows ----
    if (tid == 0)
        asm volatile("mbarrier.arrive.expect_tx.shared.b64 _, [%0], %1;"
                     :: "r"(mb), "r"(TXB) : "memory");
    if (tid < HB) {
        const int idx = __ldg(items + b * SB + ro + tid);
        bulk_cp(sv + (uint32_t)tid * VPITCH, ifac + (long long)idx * FF, 256, mb);
    } else if (tid < HB + PP) {
        const int p = tid - HB;
        const float* ubp = ufac + (long long)__ldg(user + b) * (PP * FF) + p * FF;
        bulk_cp(su + (uint32_t)p * VPITCH, ubp, 256, mb);
    }

    mbar_wait(mb);

    // ---- B fragments (U), once per warp, RNA-rounded ----
    uint32_t bf0[8], bf1[8];
    #pragma unroll
    for (int j = 0; j < 8; j++) {
        bf0[j] = lds_tf32(su + (uint32_t)gp * VPITCH + (uint32_t)((q + 8 * j) << 2));
        bf1[j] = lds_tf32(su + (uint32_t)gp * VPITCH + (uint32_t)((q + 4 + 8 * j) << 2));
    }

    // ldmatrix lane roles
    const int lrow15 = lane & 15;
    const int lhi    = lane >> 4;

    // ---- One tile per warp: tiles 0..5 at 16w, tile 6 overlapping rows 84..99 ----
    {
        const int tile = wid;                  // 0..6
        const int ts = (tile == 6) ? 84 : tile * 16;   // local start row
        const uint32_t rbase = sv + (uint32_t)((ts + lrow15) * VPITCH) + (uint32_t)(lhi << 4);

        float d0a = 0.f, d1a = 0.f, d2a = 0.f, d3a = 0.f;   // even k-steps
        float d0b = 0.f, d1b = 0.f, d2b = 0.f, d3b = 0.f;   // odd k-steps
        #pragma unroll
        for (int j = 0; j < 8; j++) {
            uint32_t a0, a1, a2, a3;
            ldsm4(a0, a1, a2, a3, rbase + (uint32_t)(j << 5));   // immediate offsets
            if (j & 1) mma_tf32(d0b, d1b, d2b, d3b, a0, a1, a2, a3, bf0[j], bf1[j]);
            else       mma_tf32(d0a, d1a, d2a, d3a, a0, a1, a2, a3, bf0[j], bf1[j]);
        }

        const int rA = ts + gp;                // local row; D frag rows gp / gp+8
        const int lo = tile * 16;              // rows < lo already emitted by tile-1
        emit_row(b, ro + rA,     q, rA     >= lo, d0a + d0b, d1a + d1b, pred, scores);
        emit_row(b, ro + rA + 8, q, rA + 8 >= lo, d2a + d2b, d3a + d3b, pred, scores);
    }
}

extern "C" void kernel_launch(void* const* d_in, const int* in_sizes, int n_in,
                              void* d_out, int out_size) {
    const int*   user  = (const int*)d_in[0];
    const int*   items = (const int*)d_in[1];
    const float* ufac  = (const float*)d_in[2];
    const float* ifac  = (const float*)d_in[3];

    const int B = in_sizes[0];

    float* out    = (float*)d_out;
    float* pred   = out;                        // [B,SB]
    float* scores = out + (long long)B * SB;    // [B,SB,PP]

    cudaFuncSetAttribute(cf_kernel, cudaFuncAttributeMaxDynamicSharedMemorySize, SMEMB);

    cf_kernel<<<2 * B, TPB, SMEMB>>>(user, items, ufac, ifac, pred, scores);
}